// round 1
// baseline (speedup 1.0000x reference)
#include <cuda_runtime.h>
#include <math.h>

#define L_  4
#define H_  12
#define E_  768
#define HS_ 64
#define V_  32000
#define B_  2
#define T_  1024
#define BT  2048
#define FF  3072

// ---------------- scratch (static device globals; no allocation APIs) --------
__device__ float g_x[BT * E_];
__device__ float g_h[BT * E_];
__device__ float g_q[BT * E_];
__device__ float g_k[BT * E_];
__device__ float g_v[BT * E_];
__device__ float g_o[BT * E_];
__device__ float g_ff[BT * FF];
__device__ float g_wq[L_ * E_ * E_];
__device__ float g_wk[L_ * E_ * E_];
__device__ float g_wv[L_ * E_ * E_];
__device__ float g_rowloss[BT];
__device__ float g_logits_scratch[(size_t)BT * V_];  // only used if d_out can't hold logits

// ---------------- repack Wq/Wk/Wv: (L,H,E,HS) -> per-layer row-major [E, H*HS]
__global__ __launch_bounds__(256) void repack_qkv_kernel(const float* __restrict__ src,
                                                         float* __restrict__ dst) {
    int i = blockIdx.x * 256 + threadIdx.x;
    if (i >= L_ * H_ * E_ * HS_) return;
    int kk = i & 63;
    int t  = i >> 6;          // (l*H + h)*E + e
    int e  = t % E_;
    int lh = t / E_;
    int h  = lh % H_;
    int l  = lh / H_;
    dst[((size_t)(l * E_ + e)) * (H_ * HS_) + h * HS_ + kk] = src[i];
}

// ---------------- embedding -------------------------------------------------
__global__ __launch_bounds__(256) void embed_kernel(const int* __restrict__ idx,
                                                    const float* __restrict__ tok,
                                                    const float* __restrict__ pos,
                                                    float* __restrict__ x) {
    int i = blockIdx.x * 256 + threadIdx.x;   // over BT*E_
    int e = i % E_;
    int t = i / E_;
    int token = idx[t];
    x[i] = tok[(size_t)token * E_ + e] + pos[(t % T_) * E_ + e];
}

// ---------------- layernorm (one row per block) -----------------------------
__global__ __launch_bounds__(256) void ln_kernel(const float* __restrict__ x,
                                                 const float* __restrict__ g,
                                                 const float* __restrict__ b,
                                                 float* __restrict__ out) {
    int row = blockIdx.x;
    int tid = threadIdx.x;
    const float* xr = x + (size_t)row * E_;
    float v[3], s = 0.f, sq = 0.f;
#pragma unroll
    for (int i = 0; i < 3; i++) {
        v[i] = xr[tid + i * 256];
        s += v[i];
        sq += v[i] * v[i];
    }
#pragma unroll
    for (int o = 16; o > 0; o >>= 1) {
        s  += __shfl_xor_sync(0xffffffffu, s, o);
        sq += __shfl_xor_sync(0xffffffffu, sq, o);
    }
    __shared__ float ss[8], ssq[8];
    if ((tid & 31) == 0) { ss[tid >> 5] = s; ssq[tid >> 5] = sq; }
    __syncthreads();
    s = 0.f; sq = 0.f;
#pragma unroll
    for (int i = 0; i < 8; i++) { s += ss[i]; sq += ssq[i]; }
    float mean = s * (1.f / E_);
    float var  = sq * (1.f / E_) - mean * mean;
    float rstd = rsqrtf(var + 1e-5f);
    float* orow = out + (size_t)row * E_;
#pragma unroll
    for (int i = 0; i < 3; i++) {
        int e = tid + i * 256;
        orow[e] = (v[i] - mean) * rstd * g[e] + b[e];
    }
}

// ---------------- generic tiled GEMM: C = A[MxK] @ B[KxN] (+bias)(+resid)(relu)
__global__ __launch_bounds__(256) void gemm_kernel(
    const float* __restrict__ A, const float* __restrict__ B,
    const float* __restrict__ bias, const float* __restrict__ resid,
    float* __restrict__ C, int M, int N, int K, int relu) {
    __shared__ float sA[16][64];
    __shared__ float sB[16][68];
    int tid  = threadIdx.x;
    int row0 = blockIdx.y << 6, col0 = blockIdx.x << 6;
    int tx = tid & 15, ty = tid >> 4;
    float acc[4][4] = {};
    const float* Ap = A + (size_t)(row0 + (tid >> 2)) * K + ((tid & 3) << 2);
    const float* Bp = B + (size_t)(tid >> 4) * N + col0 + ((tid & 15) << 2);
    int ka = (tid & 3) << 2, ma = tid >> 2;
    for (int k0 = 0; k0 < K; k0 += 16) {
        float4 a4 = *(const float4*)(Ap + k0);
        sA[ka + 0][ma] = a4.x; sA[ka + 1][ma] = a4.y;
        sA[ka + 2][ma] = a4.z; sA[ka + 3][ma] = a4.w;
        float4 b4 = *(const float4*)(Bp + (size_t)k0 * N);
        *(float4*)&sB[tid >> 4][(tid & 15) << 2] = b4;
        __syncthreads();
#pragma unroll
        for (int kk = 0; kk < 16; kk++) {
            float4 a = *(const float4*)&sA[kk][ty << 2];
            float4 b = *(const float4*)&sB[kk][tx << 2];
            acc[0][0] += a.x * b.x; acc[0][1] += a.x * b.y; acc[0][2] += a.x * b.z; acc[0][3] += a.x * b.w;
            acc[1][0] += a.y * b.x; acc[1][1] += a.y * b.y; acc[1][2] += a.y * b.z; acc[1][3] += a.y * b.w;
            acc[2][0] += a.z * b.x; acc[2][1] += a.z * b.y; acc[2][2] += a.z * b.z; acc[2][3] += a.z * b.w;
            acc[3][0] += a.w * b.x; acc[3][1] += a.w * b.y; acc[3][2] += a.w * b.z; acc[3][3] += a.w * b.w;
        }
        __syncthreads();
    }
#pragma unroll
    for (int i = 0; i < 4; i++) {
        int r = row0 + (ty << 2) + i;
#pragma unroll
        for (int j = 0; j < 4; j++) {
            int c = col0 + (tx << 2) + j;
            float vv = acc[i][j];
            if (bias)  vv += bias[c];
            if (resid) vv += resid[(size_t)r * N + c];
            if (relu)  vv = fmaxf(vv, 0.f);
            C[(size_t)r * N + c] = vv;
        }
    }
}

// ---------------- flash-style causal attention ------------------------------
// q/k/v layout: [BT, H*HS], col = h*64 + hs. Block: 64 queries of one (b,h).
__global__ __launch_bounds__(256) void attn_kernel(const float* __restrict__ q,
                                                   const float* __restrict__ k,
                                                   const float* __restrict__ v,
                                                   float* __restrict__ o) {
    __shared__ float sQP[64][64];   // Q tile, then reused as P tile
    __shared__ float sK[64][64];
    __shared__ float sVt[64][64];   // V transposed: [d][c]
    int tid = threadIdx.x;
    int qt = blockIdx.x;
    int bh = blockIdx.y;
    int b = bh / H_, h = bh % H_;
    int r = tid >> 2, quarter = tid & 3;
    int cbase = quarter << 4;
    size_t rowbase = (size_t)(b * T_ + (qt << 6));

    for (int i = tid; i < 4096; i += 256) {
        int rr = i >> 6, cc = i & 63;
        sQP[rr][cc] = q[(rowbase + rr) * (size_t)E_ + h * 64 + cc];
    }
    __syncthreads();
    float qreg[64];
#pragma unroll
    for (int i = 0; i < 16; i++) {
        float4 t4 = *(const float4*)&sQP[r][i << 2];
        qreg[i * 4 + 0] = t4.x * 0.125f; qreg[i * 4 + 1] = t4.y * 0.125f;
        qreg[i * 4 + 2] = t4.z * 0.125f; qreg[i * 4 + 3] = t4.w * 0.125f;
    }
    float m = -INFINITY, lsum = 0.f;
    float oacc[16];
#pragma unroll
    for (int j = 0; j < 16; j++) oacc[j] = 0.f;
    int qi = (qt << 6) + r;

    for (int kt = 0; kt <= qt; kt++) {
        __syncthreads();   // prior P/K/Vt consumers done
        size_t kbase = (size_t)(b * T_ + (kt << 6));
        for (int i = tid; i < 4096; i += 256) {
            int rr = i >> 6, cc = i & 63;
            float kv = k[(kbase + rr) * (size_t)E_ + h * 64 + cc];
            float vv = v[(kbase + rr) * (size_t)E_ + h * 64 + cc];
            sK[rr][cc]  = kv;
            sVt[cc][rr] = vv;
        }
        __syncthreads();

        float s[16];
#pragma unroll
        for (int j = 0; j < 16; j++) s[j] = 0.f;
#pragma unroll
        for (int kk = 0; kk < 64; kk += 4) {
#pragma unroll
            for (int j = 0; j < 16; j++) {
                float4 k4 = *(const float4*)&sK[cbase + j][kk];
                s[j] += qreg[kk] * k4.x + qreg[kk + 1] * k4.y +
                        qreg[kk + 2] * k4.z + qreg[kk + 3] * k4.w;
            }
        }
        if (kt == qt) {
#pragma unroll
            for (int j = 0; j < 16; j++)
                if ((kt << 6) + cbase + j > qi) s[j] = -INFINITY;
        }
        float mt = s[0];
#pragma unroll
        for (int j = 1; j < 16; j++) mt = fmaxf(mt, s[j]);
        mt = fmaxf(mt, __shfl_xor_sync(0xffffffffu, mt, 1));
        mt = fmaxf(mt, __shfl_xor_sync(0xffffffffu, mt, 2));
        float mnew = fmaxf(m, mt);
        float alpha = __expf(m - mnew);
        float psum = 0.f;
        float p[16];
#pragma unroll
        for (int j = 0; j < 16; j++) { p[j] = __expf(s[j] - mnew); psum += p[j]; }
        psum += __shfl_xor_sync(0xffffffffu, psum, 1);
        psum += __shfl_xor_sync(0xffffffffu, psum, 2);
        lsum = lsum * alpha + psum;
        m = mnew;
#pragma unroll
        for (int j = 0; j < 16; j++) oacc[j] *= alpha;
#pragma unroll
        for (int j = 0; j < 16; j++) sQP[r][cbase + j] = p[j];
        __syncthreads();
        // O += P @ V
#pragma unroll
        for (int c0 = 0; c0 < 64; c0 += 16) {
            float pc[16];
#pragma unroll
            for (int ii = 0; ii < 4; ii++) {
                float4 p4 = *(const float4*)&sQP[r][c0 + (ii << 2)];
                pc[ii * 4 + 0] = p4.x; pc[ii * 4 + 1] = p4.y;
                pc[ii * 4 + 2] = p4.z; pc[ii * 4 + 3] = p4.w;
            }
#pragma unroll
            for (int j = 0; j < 16; j++) {
                int d = cbase + j;
#pragma unroll
                for (int cc = 0; cc < 16; cc += 4) {
                    float4 v4 = *(const float4*)&sVt[d][c0 + cc];
                    oacc[j] += pc[cc] * v4.x + pc[cc + 1] * v4.y +
                               pc[cc + 2] * v4.z + pc[cc + 3] * v4.w;
                }
            }
        }
    }
    float linv = 1.f / lsum;
#pragma unroll
    for (int j = 0; j < 16; j++)
        o[(rowbase + r) * (size_t)E_ + h * 64 + cbase + j] = oacc[j] * linv;
}

// ---------------- loss ------------------------------------------------------
__global__ __launch_bounds__(256) void row_lse_kernel(const float* __restrict__ logits,
                                                      const int* __restrict__ targets,
                                                      float* __restrict__ rowloss) {
    int row = blockIdx.x, tid = threadIdx.x;
    const float* lr = logits + (size_t)row * V_;
    float mx = -INFINITY;
    for (int i = tid; i < V_; i += 256) mx = fmaxf(mx, lr[i]);
#pragma unroll
    for (int o = 16; o > 0; o >>= 1) mx = fmaxf(mx, __shfl_xor_sync(0xffffffffu, mx, o));
    __shared__ float sm[8];
    if ((tid & 31) == 0) sm[tid >> 5] = mx;
    __syncthreads();
    float m2 = -INFINITY;
#pragma unroll
    for (int i = 0; i < 8; i++) m2 = fmaxf(m2, sm[i]);
    float se = 0.f;
    for (int i = tid; i < V_; i += 256) se += __expf(lr[i] - m2);
#pragma unroll
    for (int o = 16; o > 0; o >>= 1) se += __shfl_xor_sync(0xffffffffu, se, o);
    __shared__ float ssum[8];
    if ((tid & 31) == 0) ssum[tid >> 5] = se;
    __syncthreads();
    if (tid == 0) {
        float tot = 0.f;
#pragma unroll
        for (int i = 0; i < 8; i++) tot += ssum[i];
        rowloss[row] = (logf(tot) + m2) - lr[targets[row]];
    }
}

__global__ __launch_bounds__(256) void loss_reduce_kernel(const float* __restrict__ rowloss,
                                                          float* __restrict__ out) {
    int tid = threadIdx.x;
    float s = 0.f;
    for (int i = tid; i < BT; i += 256) s += rowloss[i];   // fixed order: deterministic
#pragma unroll
    for (int o = 16; o > 0; o >>= 1) s += __shfl_xor_sync(0xffffffffu, s, o);
    __shared__ float sm[8];
    if ((tid & 31) == 0) sm[tid >> 5] = s;
    __syncthreads();
    if (tid == 0) {
        float t = 0.f;
#pragma unroll
        for (int i = 0; i < 8; i++) t += sm[i];
        out[0] = t * (1.f / BT);
    }
}

// ---------------- launch ----------------------------------------------------
extern "C" void kernel_launch(void* const* d_in, const int* in_sizes, int n_in,
                              void* d_out, int out_size) {
    const int*   idx     = (const int*)d_in[0];
    const int*   targets = (const int*)d_in[1];
    const float* tok_emb = (const float*)d_in[2];
    const float* pos_emb = (const float*)d_in[3];
    const float* Wq  = (const float*)d_in[4];
    const float* bq  = (const float*)d_in[5];
    const float* Wk  = (const float*)d_in[6];
    const float* bk  = (const float*)d_in[7];
    const float* Wv  = (const float*)d_in[8];
    const float* bv  = (const float*)d_in[9];
    const float* Wo  = (const float*)d_in[10];
    const float* bo  = (const float*)d_in[11];
    const float* ln1g = (const float*)d_in[12];
    const float* ln1b = (const float*)d_in[13];
    const float* W1  = (const float*)d_in[14];
    const float* b1  = (const float*)d_in[15];
    const float* W2  = (const float*)d_in[16];
    const float* b2  = (const float*)d_in[17];
    const float* ln2g = (const float*)d_in[18];
    const float* ln2b = (const float*)d_in[19];
    const float* lnfg = (const float*)d_in[20];
    const float* lnfb = (const float*)d_in[21];
    const float* Wlm = (const float*)d_in[22];
    const float* blm = (const float*)d_in[23];
    float* out = (float*)d_out;

    float *px, *ph, *pq, *pk, *pv, *po, *pff, *pwq, *pwk, *pwv, *prl, *plg;
    cudaGetSymbolAddress((void**)&px,  g_x);
    cudaGetSymbolAddress((void**)&ph,  g_h);
    cudaGetSymbolAddress((void**)&pq,  g_q);
    cudaGetSymbolAddress((void**)&pk,  g_k);
    cudaGetSymbolAddress((void**)&pv,  g_v);
    cudaGetSymbolAddress((void**)&po,  g_o);
    cudaGetSymbolAddress((void**)&pff, g_ff);
    cudaGetSymbolAddress((void**)&pwq, g_wq);
    cudaGetSymbolAddress((void**)&pwk, g_wk);
    cudaGetSymbolAddress((void**)&pwv, g_wv);
    cudaGetSymbolAddress((void**)&prl, g_rowloss);
    cudaGetSymbolAddress((void**)&plg, g_logits_scratch);

    const long long NLOG = (long long)BT * V_;
    float* logits = (out_size >= NLOG) ? out : plg;

    // repack QKV weights to row-major [E, H*HS] per layer
    int nrep = L_ * H_ * E_ * HS_;
    int grep = (nrep + 255) / 256;
    repack_qkv_kernel<<<grep, 256>>>(Wq, pwq);
    repack_qkv_kernel<<<grep, 256>>>(Wk, pwk);
    repack_qkv_kernel<<<grep, 256>>>(Wv, pwv);

    // embedding
    embed_kernel<<<(BT * E_) / 256, 256>>>(idx, tok_emb, pos_emb, px);

    dim3 gE(E_ / 64, BT / 64);    // N=768
    dim3 gF(FF / 64, BT / 64);    // N=3072
    dim3 gV(V_ / 64, BT / 64);    // N=32000
    for (int l = 0; l < L_; l++) {
        ln_kernel<<<BT, 256>>>(px, ln1g + l * E_, ln1b + l * E_, ph);
        gemm_kernel<<<gE, 256>>>(ph, pwq + (size_t)l * E_ * E_, bq + l * E_, nullptr, pq, BT, E_, E_, 0);
        gemm_kernel<<<gE, 256>>>(ph, pwk + (size_t)l * E_ * E_, bk + l * E_, nullptr, pk, BT, E_, E_, 0);
        gemm_kernel<<<gE, 256>>>(ph, pwv + (size_t)l * E_ * E_, bv + l * E_, nullptr, pv, BT, E_, E_, 0);
        attn_kernel<<<dim3(T_ / 64, B_ * H_), 256>>>(pq, pk, pv, po);
        gemm_kernel<<<gE, 256>>>(po, Wo + (size_t)l * E_ * E_, bo + l * E_, px, px, BT, E_, E_, 0);
        ln_kernel<<<BT, 256>>>(px, ln2g + l * E_, ln2b + l * E_, ph);
        gemm_kernel<<<gF, 256>>>(ph, W1 + (size_t)l * E_ * FF, b1 + l * FF, nullptr, pff, BT, FF, E_, 1);
        gemm_kernel<<<gE, 256>>>(pff, W2 + (size_t)l * FF * E_, b2 + l * E_, px, px, BT, E_, FF, 0);
    }
    ln_kernel<<<BT, 256>>>(px, lnfg, lnfb, ph);
    gemm_kernel<<<gV, 256>>>(ph, Wlm, blm, nullptr, logits, BT, V_, E_, 0);

    // loss (deterministic two-stage reduction)
    float* loss_dst = nullptr;
    if (out_size == 1)            loss_dst = out;
    else if (out_size > NLOG)     loss_dst = out + NLOG;
    if (loss_dst) {
        row_lse_kernel<<<BT, 256>>>(logits, targets, prl);
        loss_reduce_kernel<<<1, 256>>>(prl, loss_dst);
    }
}

// round 3
// speedup vs baseline: 1.4204x; 1.4204x over previous
#include <cuda_runtime.h>
#include <cuda_bf16.h>
#include <math.h>
#include <stdint.h>

#define L_  4
#define H_  12
#define E_  768
#define HS_ 64
#define V_  32000
#define B_  2
#define T_  1024
#define BT  2048
#define FF  3072
#define NQKV 2304

// ---- weight scratch offsets (elements) ----
#define WPL 7077888ull
#define OFF_QKV(l) ((size_t)(l) * WPL)
#define OFF_O(l)   (OFF_QKV(l) + 1769472ull)
#define OFF_W1(l)  (OFF_QKV(l) + 2359296ull)
#define OFF_W2(l)  (OFF_QKV(l) + 4718592ull)
#define OFF_LM     ((size_t)4 * WPL)
#define WTOT       (OFF_LM + 24576000ull)

// ---------------- scratch (static device globals; no allocation APIs) -------
__device__ float g_x[BT * E_];
__device__ float g_h[BT * E_];
__device__ float g_qkv[BT * NQKV];
__device__ float g_o[BT * E_];
__device__ float g_ff[BT * FF];
__device__ float g_wq[L_ * E_ * E_];
__device__ float g_wk[L_ * E_ * E_];
__device__ float g_wv[L_ * E_ * E_];
__device__ float g_bqkv[L_ * NQKV];
__device__ __nv_bfloat16 g_wthi[WTOT];
__device__ __nv_bfloat16 g_wtlo[WTOT];
__device__ float g_rowloss[BT];
__device__ float g_logits_scratch[(size_t)BT * V_];

// ---------------- PTX helpers (all non-'a' features) -------------------------
__device__ __forceinline__ uint32_t smem_u32(const void* p) {
    uint32_t a;
    asm("{ .reg .u64 t; cvta.to.shared.u64 t, %1; cvt.u32.u64 %0, t; }" : "=r"(a) : "l"(p));
    return a;
}
__device__ __forceinline__ void mma16816(float* c, const uint32_t* a, const uint32_t* b) {
    asm volatile(
        "mma.sync.aligned.m16n8k16.row.col.f32.bf16.bf16.f32 "
        "{%0,%1,%2,%3}, {%4,%5,%6,%7}, {%8,%9}, {%0,%1,%2,%3};"
        : "+f"(c[0]), "+f"(c[1]), "+f"(c[2]), "+f"(c[3])
        : "r"(a[0]), "r"(a[1]), "r"(a[2]), "r"(a[3]), "r"(b[0]), "r"(b[1]));
}
__device__ __forceinline__ void ldsm4(uint32_t* r, uint32_t addr) {
    asm volatile("ldmatrix.sync.aligned.m8n8.x4.shared.b16 {%0,%1,%2,%3}, [%4];"
                 : "=r"(r[0]), "=r"(r[1]), "=r"(r[2]), "=r"(r[3]) : "r"(addr));
}
__device__ __forceinline__ void cpasync16(uint32_t dst, const void* src) {
    asm volatile("cp.async.cg.shared.global [%0], [%1], 16;" :: "r"(dst), "l"(src));
}
__device__ __forceinline__ uint32_t bf2u(__nv_bfloat162 h) {
    return *reinterpret_cast<uint32_t*>(&h);
}

// ---------------- repack Wq/Wk/Wv: (L,H,E,HS) -> per-layer [E, H*HS] fp32 ----
__global__ __launch_bounds__(256) void repack_qkv_kernel(const float* __restrict__ src,
                                                         float* __restrict__ dst) {
    int i = blockIdx.x * 256 + threadIdx.x;
    if (i >= L_ * H_ * E_ * HS_) return;
    int kk = i & 63;
    int t  = i >> 6;
    int e  = t % E_;
    int lh = t / E_;
    int h  = lh % H_;
    int l  = lh / H_;
    dst[((size_t)(l * E_ + e)) * (H_ * HS_) + h * HS_ + kk] = src[i];
}

// ---------------- weight transpose + bf16 hi/lo split ------------------------
// W[K,N] fp32 -> Wt[N,K] bf16 hi/lo.  block (32,8), grid (N/32, K/32)
__global__ __launch_bounds__(256) void wconvt_kernel(const float* __restrict__ W,
                                                     __nv_bfloat16* __restrict__ Whi,
                                                     __nv_bfloat16* __restrict__ Wlo,
                                                     int K, int N) {
    __shared__ float s[32][33];
    int k0 = blockIdx.y * 32, n0 = blockIdx.x * 32;
    int tx = threadIdx.x, ty = threadIdx.y;
#pragma unroll
    for (int i = 0; i < 4; i++)
        s[ty + 8 * i][tx] = W[(size_t)(k0 + ty + 8 * i) * N + n0 + tx];
    __syncthreads();
#pragma unroll
    for (int i = 0; i < 4; i++) {
        int n = ty + 8 * i;
        float x = s[tx][n];                 // = W[k0+tx][n0+n]
        __nv_bfloat16 h = __float2bfloat16(x);
        __nv_bfloat16 l = __float2bfloat16(x - __bfloat162float(h));
        size_t oi = (size_t)(n0 + n) * K + k0 + tx;
        Whi[oi] = h;
        Wlo[oi] = l;
    }
}

// ---------------- concat qkv bias -------------------------------------------
__global__ __launch_bounds__(256) void biascat_kernel(const float* __restrict__ bq,
                                                      const float* __restrict__ bk,
                                                      const float* __restrict__ bv,
                                                      float* __restrict__ out) {
    int i = blockIdx.x * 256 + threadIdx.x;
    if (i >= L_ * NQKV) return;
    int l = i / NQKV, c = i % NQKV;
    float v;
    if (c < E_)            v = bq[l * E_ + c];
    else if (c < 2 * E_)   v = bk[l * E_ + c - E_];
    else                   v = bv[l * E_ + c - 2 * E_];
    out[i] = v;
}

// ---------------- embedding -------------------------------------------------
__global__ __launch_bounds__(256) void embed_kernel(const int* __restrict__ idx,
                                                    const float* __restrict__ tok,
                                                    const float* __restrict__ pos,
                                                    float* __restrict__ x) {
    int i = blockIdx.x * 256 + threadIdx.x;
    int e = i % E_;
    int t = i / E_;
    int token = idx[t];
    x[i] = tok[(size_t)token * E_ + e] + pos[(t % T_) * E_ + e];
}

// ---------------- layernorm -------------------------------------------------
__global__ __launch_bounds__(256) void ln_kernel(const float* __restrict__ x,
                                                 const float* __restrict__ g,
                                                 const float* __restrict__ b,
                                                 float* __restrict__ out) {
    int row = blockIdx.x;
    int tid = threadIdx.x;
    const float* xr = x + (size_t)row * E_;
    float v[3], s = 0.f, sq = 0.f;
#pragma unroll
    for (int i = 0; i < 3; i++) {
        v[i] = xr[tid + i * 256];
        s += v[i];
        sq += v[i] * v[i];
    }
#pragma unroll
    for (int o = 16; o > 0; o >>= 1) {
        s  += __shfl_xor_sync(0xffffffffu, s, o);
        sq += __shfl_xor_sync(0xffffffffu, sq, o);
    }
    __shared__ float ss[8], ssq[8];
    if ((tid & 31) == 0) { ss[tid >> 5] = s; ssq[tid >> 5] = sq; }
    __syncthreads();
    s = 0.f; sq = 0.f;
#pragma unroll
    for (int i = 0; i < 8; i++) { s += ss[i]; sq += ssq[i]; }
    float mean = s * (1.f / E_);
    float var  = sq * (1.f / E_) - mean * mean;
    float rstd = rsqrtf(var + 1e-5f);
    float* orow = out + (size_t)row * E_;
#pragma unroll
    for (int i = 0; i < 3; i++) {
        int e = tid + i * 256;
        orow[e] = (v[i] - mean) * rstd * g[e] + b[e];
    }
}

// ---------------- tensor-core GEMM via mma.sync (bf16 hi/lo, fp32 acc) -------
// C[M,N] = A[M,K] @ Wt[N,K]^T (+bias)(+resid)(relu)
// 128x128 CTA tile, BK=32, 256 threads (8 warps 2x4), warp tile 64x32.
// smem per stage (bytes): Ahi[128*80], Alo, Bhi, Blo  => 40960; 2 stages.
#define STG 40960
#define GEMM_SMEM (2 * STG)
__global__ __launch_bounds__(256, 1)
void gemm_tc_kernel(const float* __restrict__ A,
                    const __nv_bfloat16* __restrict__ WThi,
                    const __nv_bfloat16* __restrict__ WTlo,
                    const float* __restrict__ bias,
                    const float* __restrict__ resid,
                    float* __restrict__ C,
                    int N, int K, int relu) {
    extern __shared__ __align__(16) char smem[];
    int tid = threadIdx.x, lane = tid & 31, wid = tid >> 5;
    int wm = wid >> 2, wn = wid & 3;
    int row0 = blockIdx.y << 7, col0 = blockIdx.x << 7;
    uint32_t sb = smem_u32(smem);

    float acc[4][4][4] = {};

    auto loadA = [&](int st, int k0) {
        char* s = smem + st * STG;
#pragma unroll
        for (int i = 0; i < 4; i++) {
            int idx = tid + (i << 8);
            int row = idx >> 3, c4 = idx & 7;
            float4 x = *(const float4*)(A + (size_t)(row0 + row) * K + k0 + (c4 << 2));
            __nv_bfloat162 h0 = __floats2bfloat162_rn(x.x, x.y);
            __nv_bfloat162 h1 = __floats2bfloat162_rn(x.z, x.w);
            float2 f0 = __bfloat1622float2(h0), f1 = __bfloat1622float2(h1);
            __nv_bfloat162 l0 = __floats2bfloat162_rn(x.x - f0.x, x.y - f0.y);
            __nv_bfloat162 l1 = __floats2bfloat162_rn(x.z - f1.x, x.w - f1.y);
            *(uint2*)(s + row * 80 + (c4 << 3))         = make_uint2(bf2u(h0), bf2u(h1));
            *(uint2*)(s + 10240 + row * 80 + (c4 << 3)) = make_uint2(bf2u(l0), bf2u(l1));
        }
    };
    auto loadB = [&](int st, int k0) {
        uint32_t s = sb + st * STG + 20480;
#pragma unroll
        for (int i = 0; i < 2; i++) {
            int seg = tid + (i << 8);
            int row = seg >> 2, sg = seg & 3;
            size_t gi = (size_t)(col0 + row) * K + k0 + (sg << 3);
            uint32_t d = s + row * 80 + (sg << 4);
            cpasync16(d,         WThi + gi);
            cpasync16(d + 10240, WTlo + gi);
        }
    };

    const int nCh = K >> 5;
    loadA(0, 0);
    loadB(0, 0);
    asm volatile("cp.async.commit_group;" ::: "memory");
    for (int c = 0; c < nCh; ++c) {
        int st = c & 1;
        if (c + 1 < nCh) {
            loadA(st ^ 1, (c + 1) << 5);
            loadB(st ^ 1, (c + 1) << 5);
            asm volatile("cp.async.commit_group;" ::: "memory");
            asm volatile("cp.async.wait_group 1;" ::: "memory");
        } else {
            asm volatile("cp.async.wait_group 0;" ::: "memory");
        }
        __syncthreads();

        uint32_t sA = sb + st * STG;
        const char* sBc = smem + st * STG + 20480;
#pragma unroll
        for (int ks = 0; ks < 2; ks++) {
            uint32_t ah[4][4], al[4][4];
            int arow = (wm << 6) + (lane & 15);
            int acol = (ks << 4) + ((lane >> 4) << 3);
#pragma unroll
            for (int mf = 0; mf < 4; mf++) {
                uint32_t addr = sA + (uint32_t)(arow + (mf << 4)) * 80 + (uint32_t)(acol << 1);
                ldsm4(ah[mf], addr);
                ldsm4(al[mf], addr + 10240);
            }
            uint32_t bh[4][2], bl[4][2];
            int brow = (wn << 5) + (lane >> 2);
            int bcol = (ks << 4) + ((lane & 3) << 1);
#pragma unroll
            for (int nf = 0; nf < 4; nf++) {
                const char* ba = sBc + (brow + (nf << 3)) * 80 + (bcol << 1);
                bh[nf][0] = *(const uint32_t*)(ba);
                bh[nf][1] = *(const uint32_t*)(ba + 16);
                bl[nf][0] = *(const uint32_t*)(ba + 10240);
                bl[nf][1] = *(const uint32_t*)(ba + 10256);
            }
#pragma unroll
            for (int mf = 0; mf < 4; mf++)
#pragma unroll
                for (int nf = 0; nf < 4; nf++) {
                    mma16816(acc[mf][nf], ah[mf], bh[nf]);
                    mma16816(acc[mf][nf], ah[mf], bl[nf]);
                    mma16816(acc[mf][nf], al[mf], bh[nf]);
                }
        }
        __syncthreads();
    }

    // epilogue: fused bias/resid/relu, 8B stores (full 32B sectors per frag row)
#pragma unroll
    for (int mf = 0; mf < 4; mf++) {
        int rbase = row0 + (wm << 6) + (mf << 4) + (lane >> 2);
#pragma unroll
        for (int nf = 0; nf < 4; nf++) {
            int cb = col0 + (wn << 5) + (nf << 3) + ((lane & 3) << 1);
            float b0 = 0.f, b1 = 0.f;
            if (bias) { b0 = bias[cb]; b1 = bias[cb + 1]; }
#pragma unroll
            for (int half = 0; half < 2; half++) {
                int r = rbase + (half << 3);
                float v0 = acc[mf][nf][half * 2 + 0] + b0;
                float v1 = acc[mf][nf][half * 2 + 1] + b1;
                size_t gi = (size_t)r * N + cb;
                if (resid) { v0 += resid[gi]; v1 += resid[gi + 1]; }
                if (relu)  { v0 = fmaxf(v0, 0.f); v1 = fmaxf(v1, 0.f); }
                *(float2*)(C + gi) = make_float2(v0, v1);
            }
        }
    }
}

// ---------------- flash-style causal attention (fp32) ------------------------
// q/k/v live in g_qkv [BT, 2304]: q at col h*64, k at 768+h*64, v at 1536+h*64
__global__ __launch_bounds__(256) void attn_kernel(const float* __restrict__ qkv,
                                                   float* __restrict__ o) {
    __shared__ float sQP[64][64];
    __shared__ float sK[64][64];
    __shared__ float sVt[64][64];
    int tid = threadIdx.x;
    int qt = blockIdx.x;
    int bh = blockIdx.y;
    int b = bh / H_, h = bh % H_;
    int r = tid >> 2, quarter = tid & 3;
    int cbase = quarter << 4;
    size_t rowbase = (size_t)(b * T_ + (qt << 6));
    const float* q = qkv + h * 64;
    const float* k = qkv + E_ + h * 64;
    const float* v = qkv + 2 * E_ + h * 64;

    for (int i = tid; i < 4096; i += 256) {
        int rr = i >> 6, cc = i & 63;
        sQP[rr][cc] = q[(rowbase + rr) * (size_t)NQKV + cc];
    }
    __syncthreads();
    float qreg[64];
#pragma unroll
    for (int i = 0; i < 16; i++) {
        float4 t4 = *(const float4*)&sQP[r][i << 2];
        qreg[i * 4 + 0] = t4.x * 0.125f; qreg[i * 4 + 1] = t4.y * 0.125f;
        qreg[i * 4 + 2] = t4.z * 0.125f; qreg[i * 4 + 3] = t4.w * 0.125f;
    }
    float m = -INFINITY, lsum = 0.f;
    float oacc[16];
#pragma unroll
    for (int j = 0; j < 16; j++) oacc[j] = 0.f;
    int qi = (qt << 6) + r;

    for (int kt = 0; kt <= qt; kt++) {
        __syncthreads();
        size_t kbase = (size_t)(b * T_ + (kt << 6));
        for (int i = tid; i < 4096; i += 256) {
            int rr = i >> 6, cc = i & 63;
            float kv = k[(kbase + rr) * (size_t)NQKV + cc];
            float vv = v[(kbase + rr) * (size_t)NQKV + cc];
            sK[rr][cc]  = kv;
            sVt[cc][rr] = vv;
        }
        __syncthreads();

        float s[16];
#pragma unroll
        for (int j = 0; j < 16; j++) s[j] = 0.f;
#pragma unroll
        for (int kk = 0; kk < 64; kk += 4) {
#pragma unroll
            for (int j = 0; j < 16; j++) {
                float4 k4 = *(const float4*)&sK[cbase + j][kk];
                s[j] += qreg[kk] * k4.x + qreg[kk + 1] * k4.y +
                        qreg[kk + 2] * k4.z + qreg[kk + 3] * k4.w;
            }
        }
        if (kt == qt) {
#pragma unroll
            for (int j = 0; j < 16; j++)
                if ((kt << 6) + cbase + j > qi) s[j] = -INFINITY;
        }
        float mt = s[0];
#pragma unroll
        for (int j = 1; j < 16; j++) mt = fmaxf(mt, s[j]);
        mt = fmaxf(mt, __shfl_xor_sync(0xffffffffu, mt, 1));
        mt = fmaxf(mt, __shfl_xor_sync(0xffffffffu, mt, 2));
        float mnew = fmaxf(m, mt);
        float alpha = __expf(m - mnew);
        float psum = 0.f;
        float p[16];
#pragma unroll
        for (int j = 0; j < 16; j++) { p[j] = __expf(s[j] - mnew); psum += p[j]; }
        psum += __shfl_xor_sync(0xffffffffu, psum, 1);
        psum += __shfl_xor_sync(0xffffffffu, psum, 2);
        lsum = lsum * alpha + psum;
        m = mnew;
#pragma unroll
        for (int j = 0; j < 16; j++) oacc[j] *= alpha;
#pragma unroll
        for (int j = 0; j < 16; j++) sQP[r][cbase + j] = p[j];
        __syncthreads();
#pragma unroll
        for (int c0 = 0; c0 < 64; c0 += 16) {
            float pc[16];
#pragma unroll
            for (int ii = 0; ii < 4; ii++) {
                float4 p4 = *(const float4*)&sQP[r][c0 + (ii << 2)];
                pc[ii * 4 + 0] = p4.x; pc[ii * 4 + 1] = p4.y;
                pc[ii * 4 + 2] = p4.z; pc[ii * 4 + 3] = p4.w;
            }
#pragma unroll
            for (int j = 0; j < 16; j++) {
                int d = cbase + j;
#pragma unroll
                for (int cc = 0; cc < 16; cc += 4) {
                    float4 v4 = *(const float4*)&sVt[d][c0 + cc];
                    oacc[j] += pc[cc] * v4.x + pc[cc + 1] * v4.y +
                               pc[cc + 2] * v4.z + pc[cc + 3] * v4.w;
                }
            }
        }
    }
    float linv = 1.f / lsum;
#pragma unroll
    for (int j = 0; j < 16; j++)
        o[(rowbase + r) * (size_t)E_ + h * 64 + cbase + j] = oacc[j] * linv;
}

// ---------------- loss ------------------------------------------------------
__global__ __launch_bounds__(256) void row_lse_kernel(const float* __restrict__ logits,
                                                      const int* __restrict__ targets,
                                                      float* __restrict__ rowloss) {
    int row = blockIdx.x, tid = threadIdx.x;
    const float* lr = logits + (size_t)row * V_;
    float mx = -INFINITY;
    for (int i = tid; i < V_; i += 256) mx = fmaxf(mx, lr[i]);
#pragma unroll
    for (int o = 16; o > 0; o >>= 1) mx = fmaxf(mx, __shfl_xor_sync(0xffffffffu, mx, o));
    __shared__ float sm[8];
    if ((tid & 31) == 0) sm[tid >> 5] = mx;
    __syncthreads();
    float m2 = -INFINITY;
#pragma unroll
    for (int i = 0; i < 8; i++) m2 = fmaxf(m2, sm[i]);
    float se = 0.f;
    for (int i = tid; i < V_; i += 256) se += __expf(lr[i] - m2);
#pragma unroll
    for (int o = 16; o > 0; o >>= 1) se += __shfl_xor_sync(0xffffffffu, se, o);
    __shared__ float ssum[8];
    if ((tid & 31) == 0) ssum[tid >> 5] = se;
    __syncthreads();
    if (tid == 0) {
        float tot = 0.f;
#pragma unroll
        for (int i = 0; i < 8; i++) tot += ssum[i];
        rowloss[row] = (logf(tot) + m2) - lr[targets[row]];
    }
}

__global__ __launch_bounds__(256) void loss_reduce_kernel(const float* __restrict__ rowloss,
                                                          float* __restrict__ out) {
    int tid = threadIdx.x;
    float s = 0.f;
    for (int i = tid; i < BT; i += 256) s += rowloss[i];
#pragma unroll
    for (int o = 16; o > 0; o >>= 1) s += __shfl_xor_sync(0xffffffffu, s, o);
    __shared__ float sm[8];
    if ((tid & 31) == 0) sm[tid >> 5] = s;
    __syncthreads();
    if (tid == 0) {
        float t = 0.f;
#pragma unroll
        for (int i = 0; i < 8; i++) t += sm[i];
        out[0] = t * (1.f / BT);
    }
}

// ---------------- launch ----------------------------------------------------
extern "C" void kernel_launch(void* const* d_in, const int* in_sizes, int n_in,
                              void* d_out, int out_size) {
    const int*   idx     = (const int*)d_in[0];
    const int*   targets = (const int*)d_in[1];
    const float* tok_emb = (const float*)d_in[2];
    const float* pos_emb = (const float*)d_in[3];
    const float* Wq  = (const float*)d_in[4];
    const float* bq  = (const float*)d_in[5];
    const float* Wk  = (const float*)d_in[6];
    const float* bk  = (const float*)d_in[7];
    const float* Wv  = (const float*)d_in[8];
    const float* bv  = (const float*)d_in[9];
    const float* Wo  = (const float*)d_in[10];
    const float* bo  = (const float*)d_in[11];
    const float* ln1g = (const float*)d_in[12];
    const float* ln1b = (const float*)d_in[13];
    const float* W1  = (const float*)d_in[14];
    const float* b1  = (const float*)d_in[15];
    const float* W2  = (const float*)d_in[16];
    const float* b2  = (const float*)d_in[17];
    const float* ln2g = (const float*)d_in[18];
    const float* ln2b = (const float*)d_in[19];
    const float* lnfg = (const float*)d_in[20];
    const float* lnfb = (const float*)d_in[21];
    const float* Wlm = (const float*)d_in[22];
    const float* blm = (const float*)d_in[23];
    float* out = (float*)d_out;

    float *px, *ph, *pqkv, *po, *pff, *pwq, *pwk, *pwv, *pbqkv, *prl, *plg;
    __nv_bfloat16 *pwthi, *pwtlo;
    cudaGetSymbolAddress((void**)&px,    g_x);
    cudaGetSymbolAddress((void**)&ph,    g_h);
    cudaGetSymbolAddress((void**)&pqkv,  g_qkv);
    cudaGetSymbolAddress((void**)&po,    g_o);
    cudaGetSymbolAddress((void**)&pff,   g_ff);
    cudaGetSymbolAddress((void**)&pwq,   g_wq);
    cudaGetSymbolAddress((void**)&pwk,   g_wk);
    cudaGetSymbolAddress((void**)&pwv,   g_wv);
    cudaGetSymbolAddress((void**)&pbqkv, g_bqkv);
    cudaGetSymbolAddress((void**)&pwthi, g_wthi);
    cudaGetSymbolAddress((void**)&pwtlo, g_wtlo);
    cudaGetSymbolAddress((void**)&prl,   g_rowloss);
    cudaGetSymbolAddress((void**)&plg,   g_logits_scratch);

    cudaFuncSetAttribute(gemm_tc_kernel, cudaFuncAttributeMaxDynamicSharedMemorySize, GEMM_SMEM);

    const long long NLOG = (long long)BT * V_;
    float* logits = (out_size >= NLOG) ? out : plg;

    // --- weight prep ---
    int nrep = L_ * H_ * E_ * HS_;
    int grep = (nrep + 255) / 256;
    repack_qkv_kernel<<<grep, 256>>>(Wq, pwq);
    repack_qkv_kernel<<<grep, 256>>>(Wk, pwk);
    repack_qkv_kernel<<<grep, 256>>>(Wv, pwv);
    biascat_kernel<<<(L_ * NQKV + 255) / 256, 256>>>(bq, bk, bv, pbqkv);

    dim3 cb(32, 8);
    for (int l = 0; l < L_; l++) {
        size_t wel = (size_t)l * E_ * E_;
        wconvt_kernel<<<dim3(E_ / 32, E_ / 32), cb>>>(pwq + wel, pwthi + OFF_QKV(l),           pwtlo + OFF_QKV(l),           E_, E_);
        wconvt_kernel<<<dim3(E_ / 32, E_ / 32), cb>>>(pwk + wel, pwthi + OFF_QKV(l) + 589824,  pwtlo + OFF_QKV(l) + 589824,  E_, E_);
        wconvt_kernel<<<dim3(E_ / 32, E_ / 32), cb>>>(pwv + wel, pwthi + OFF_QKV(l) + 1179648, pwtlo + OFF_QKV(l) + 1179648, E_, E_);
        wconvt_kernel<<<dim3(E_ / 32, E_ / 32), cb>>>(Wo + wel,  pwthi + OFF_O(l),             pwtlo + OFF_O(l),             E_, E_);
        wconvt_kernel<<<dim3(FF / 32, E_ / 32), cb>>>(W1 + (size_t)l * E_ * FF, pwthi + OFF_W1(l), pwtlo + OFF_W1(l), E_, FF);
        wconvt_kernel<<<dim3(E_ / 32, FF / 32), cb>>>(W2 + (size_t)l * FF * E_, pwthi + OFF_W2(l), pwtlo + OFF_W2(l), FF, E_);
    }
    wconvt_kernel<<<dim3(V_ / 32, E_ / 32), cb>>>(Wlm, pwthi + OFF_LM, pwtlo + OFF_LM, E_, V_);

    // --- forward ---
    embed_kernel<<<(BT * E_) / 256, 256>>>(idx, tok_emb, pos_emb, px);

    dim3 gQKV(NQKV / 128, BT / 128);
    dim3 gE(E_ / 128, BT / 128);
    dim3 gF(FF / 128, BT / 128);
    dim3 gV(V_ / 128, BT / 128);
    for (int l = 0; l < L_; l++) {
        ln_kernel<<<BT, 256>>>(px, ln1g + l * E_, ln1b + l * E_, ph);
        gemm_tc_kernel<<<gQKV, 256, GEMM_SMEM>>>(ph, pwthi + OFF_QKV(l), pwtlo + OFF_QKV(l),
                                                 pbqkv + l * NQKV, nullptr, pqkv, NQKV, E_, 0);
        attn_kernel<<<dim3(T_ / 64, B_ * H_), 256>>>(pqkv, po);
        gemm_tc_kernel<<<gE, 256, GEMM_SMEM>>>(po, pwthi + OFF_O(l), pwtlo + OFF_O(l),
                                               bo + l * E_, px, px, E_, E_, 0);
        ln_kernel<<<BT, 256>>>(px, ln2g + l * E_, ln2b + l * E_, ph);
        gemm_tc_kernel<<<gF, 256, GEMM_SMEM>>>(ph, pwthi + OFF_W1(l), pwtlo + OFF_W1(l),
                                               b1 + l * FF, nullptr, pff, FF, E_, 1);
        gemm_tc_kernel<<<gE, 256, GEMM_SMEM>>>(pff, pwthi + OFF_W2(l), pwtlo + OFF_W2(l),
                                               b2 + l * E_, px, px, E_, FF, 0);
    }
    ln_kernel<<<BT, 256>>>(px, lnfg, lnfb, ph);
    gemm_tc_kernel<<<gV, 256, GEMM_SMEM>>>(ph, pwthi + OFF_LM, pwtlo + OFF_LM,
                                           blm, nullptr, logits, V_, E_, 0);

    // --- loss ---
    float* loss_dst = nullptr;
    if (out_size == 1)        loss_dst = out;
    else if (out_size > NLOG) loss_dst = out + NLOG;
    if (loss_dst) {
        row_lse_kernel<<<BT, 256>>>(logits, targets, prl);
        loss_reduce_kernel<<<1, 256>>>(prl, loss_dst);
    }
}

// round 4
// speedup vs baseline: 1.4808x; 1.0425x over previous
#include <cuda_runtime.h>
#include <cuda_bf16.h>
#include <math.h>
#include <stdint.h>

#define L_  4
#define H_  12
#define E_  768
#define HS_ 64
#define V_  32000
#define B_  2
#define T_  1024
#define BT  2048
#define FF  3072
#define NQKV 2304

// ---- weight scratch offsets (elements) ----
#define WPL 7077888ull
#define OFF_QKV(l) ((size_t)(l) * WPL)
#define OFF_O(l)   (OFF_QKV(l) + 1769472ull)
#define OFF_W1(l)  (OFF_QKV(l) + 2359296ull)
#define OFF_W2(l)  (OFF_QKV(l) + 4718592ull)
#define OFF_LM     ((size_t)4 * WPL)
#define WTOT       (OFF_LM + 24576000ull)

// ---------------- scratch (static device globals) ----------------------------
__device__ float g_x[BT * E_];
__device__ float g_qkv[BT * NQKV];
__device__ __nv_bfloat16 g_hhi[BT * E_];
__device__ __nv_bfloat16 g_hlo[BT * E_];
__device__ __nv_bfloat16 g_ohi[BT * E_];
__device__ __nv_bfloat16 g_olo[BT * E_];
__device__ __nv_bfloat16 g_ffhi[BT * FF];
__device__ __nv_bfloat16 g_fflo[BT * FF];
__device__ float g_wq[L_ * E_ * E_];
__device__ float g_wk[L_ * E_ * E_];
__device__ float g_wv[L_ * E_ * E_];
__device__ float g_bqkv[L_ * NQKV];
__device__ __nv_bfloat16 g_wthi[WTOT];
__device__ __nv_bfloat16 g_wtlo[WTOT];
__device__ float g_rowloss[BT];
__device__ float g_logits_scratch[(size_t)BT * V_];

// ---------------- PTX helpers (all non-'a' features) -------------------------
__device__ __forceinline__ uint32_t smem_u32(const void* p) {
    uint32_t a;
    asm("{ .reg .u64 t; cvta.to.shared.u64 t, %1; cvt.u32.u64 %0, t; }" : "=r"(a) : "l"(p));
    return a;
}
__device__ __forceinline__ void mma16816(float* c, const uint32_t* a, uint32_t b0, uint32_t b1) {
    asm volatile(
        "mma.sync.aligned.m16n8k16.row.col.f32.bf16.bf16.f32 "
        "{%0,%1,%2,%3}, {%4,%5,%6,%7}, {%8,%9}, {%0,%1,%2,%3};"
        : "+f"(c[0]), "+f"(c[1]), "+f"(c[2]), "+f"(c[3])
        : "r"(a[0]), "r"(a[1]), "r"(a[2]), "r"(a[3]), "r"(b0), "r"(b1));
}
__device__ __forceinline__ void ldsm4(uint32_t* r, uint32_t addr) {
    asm volatile("ldmatrix.sync.aligned.m8n8.x4.shared.b16 {%0,%1,%2,%3}, [%4];"
                 : "=r"(r[0]), "=r"(r[1]), "=r"(r[2]), "=r"(r[3]) : "r"(addr));
}
__device__ __forceinline__ void cpasync16(uint32_t dst, const void* src) {
    asm volatile("cp.async.cg.shared.global [%0], [%1], 16;" :: "r"(dst), "l"(src));
}
__device__ __forceinline__ uint32_t bf2u(__nv_bfloat162 h) {
    return *reinterpret_cast<uint32_t*>(&h);
}

// ---------------- repack Wq/Wk/Wv: (L,H,E,HS) -> per-layer [E, H*HS] fp32 ----
__global__ __launch_bounds__(256) void repack_qkv_kernel(const float* __restrict__ src,
                                                         float* __restrict__ dst) {
    int i = blockIdx.x * 256 + threadIdx.x;
    if (i >= L_ * H_ * E_ * HS_) return;
    int kk = i & 63;
    int t  = i >> 6;
    int e  = t % E_;
    int lh = t / E_;
    int h  = lh % H_;
    int l  = lh / H_;
    dst[((size_t)(l * E_ + e)) * (H_ * HS_) + h * HS_ + kk] = src[i];
}

// ---------------- weight transpose + bf16 hi/lo split ------------------------
__global__ __launch_bounds__(256) void wconvt_kernel(const float* __restrict__ W,
                                                     __nv_bfloat16* __restrict__ Whi,
                                                     __nv_bfloat16* __restrict__ Wlo,
                                                     int K, int N) {
    __shared__ float s[32][33];
    int k0 = blockIdx.y * 32, n0 = blockIdx.x * 32;
    int tx = threadIdx.x, ty = threadIdx.y;
#pragma unroll
    for (int i = 0; i < 4; i++)
        s[ty + 8 * i][tx] = W[(size_t)(k0 + ty + 8 * i) * N + n0 + tx];
    __syncthreads();
#pragma unroll
    for (int i = 0; i < 4; i++) {
        int n = ty + 8 * i;
        float x = s[tx][n];
        __nv_bfloat16 h = __float2bfloat16(x);
        __nv_bfloat16 l = __float2bfloat16(x - __bfloat162float(h));
        size_t oi = (size_t)(n0 + n) * K + k0 + tx;
        Whi[oi] = h;
        Wlo[oi] = l;
    }
}

// ---------------- concat qkv bias -------------------------------------------
__global__ __launch_bounds__(256) void biascat_kernel(const float* __restrict__ bq,
                                                      const float* __restrict__ bk,
                                                      const float* __restrict__ bv,
                                                      float* __restrict__ out) {
    int i = blockIdx.x * 256 + threadIdx.x;
    if (i >= L_ * NQKV) return;
    int l = i / NQKV, c = i % NQKV;
    float v;
    if (c < E_)            v = bq[l * E_ + c];
    else if (c < 2 * E_)   v = bk[l * E_ + c - E_];
    else                   v = bv[l * E_ + c - 2 * E_];
    out[i] = v;
}

// ---------------- embedding -------------------------------------------------
__global__ __launch_bounds__(256) void embed_kernel(const int* __restrict__ idx,
                                                    const float* __restrict__ tok,
                                                    const float* __restrict__ pos,
                                                    float* __restrict__ x) {
    int i = blockIdx.x * 256 + threadIdx.x;
    int e = i % E_;
    int t = i / E_;
    int token = idx[t];
    x[i] = tok[(size_t)token * E_ + e] + pos[(t % T_) * E_ + e];
}

// ---------------- layernorm -> bf16 hi/lo ------------------------------------
__global__ __launch_bounds__(256) void ln_kernel(const float* __restrict__ x,
                                                 const float* __restrict__ g,
                                                 const float* __restrict__ b,
                                                 __nv_bfloat16* __restrict__ hi,
                                                 __nv_bfloat16* __restrict__ lo) {
    int row = blockIdx.x;
    int tid = threadIdx.x;
    const float* xr = x + (size_t)row * E_;
    float v[3], s = 0.f, sq = 0.f;
#pragma unroll
    for (int i = 0; i < 3; i++) {
        v[i] = xr[tid + i * 256];
        s += v[i];
        sq += v[i] * v[i];
    }
#pragma unroll
    for (int o = 16; o > 0; o >>= 1) {
        s  += __shfl_xor_sync(0xffffffffu, s, o);
        sq += __shfl_xor_sync(0xffffffffu, sq, o);
    }
    __shared__ float ss[8], ssq[8];
    if ((tid & 31) == 0) { ss[tid >> 5] = s; ssq[tid >> 5] = sq; }
    __syncthreads();
    s = 0.f; sq = 0.f;
#pragma unroll
    for (int i = 0; i < 8; i++) { s += ss[i]; sq += ssq[i]; }
    float mean = s * (1.f / E_);
    float var  = sq * (1.f / E_) - mean * mean;
    float rstd = rsqrtf(var + 1e-5f);
    size_t rb = (size_t)row * E_;
#pragma unroll
    for (int i = 0; i < 3; i++) {
        int e = tid + i * 256;
        float y = (v[i] - mean) * rstd * g[e] + b[e];
        __nv_bfloat16 h = __float2bfloat16(y);
        hi[rb + e] = h;
        lo[rb + e] = __float2bfloat16(y - __bfloat162float(h));
    }
}

// ---------------- tensor-core GEMM (bf16 hi/lo, all-cp.async, 3 stages) ------
// C[M,N] = A @ Wt^T; A,B pre-split bf16 hi/lo, [M,K]/[N,K].
// 128x128 CTA, BK=32, 256 thr (8 warps, wm in {0,1} x wn in {0..3}), warp 64x32.
// smem stage (32KB): Ahi@0, Alo@8192, Bhi@16384, Blo@24576.
// 64B rows, 16B-chunk swizzle: phys = chunk ^ ((row>>1)&3).
#define STG3 32768
#define GEMM_SMEM (3 * STG3)
__global__ __launch_bounds__(256, 2)
void gemm_tc_kernel(const __nv_bfloat16* __restrict__ Ahi,
                    const __nv_bfloat16* __restrict__ Alo,
                    const __nv_bfloat16* __restrict__ Bhi,
                    const __nv_bfloat16* __restrict__ Blo,
                    const float* __restrict__ bias,
                    const float* __restrict__ resid,
                    float* __restrict__ C,
                    __nv_bfloat16* __restrict__ Chi,
                    __nv_bfloat16* __restrict__ Clo,
                    int N, int K, int relu) {
    extern __shared__ __align__(16) char smem[];
    int tid = threadIdx.x, lane = tid & 31, wid = tid >> 5;
    int wm = wid >> 2, wn = wid & 3;
    int row0 = blockIdx.y << 7, col0 = blockIdx.x << 7;
    uint32_t sb = smem_u32(smem);

    float acc[2][4][4][4] = {};   // [mf_pair? no] -> use [4][4][4] ; keep flat
    // (we use acc4 below; placeholder removed)
    float (*accv)[4][4] = acc[0]; // alias: acc[0] is [4][4][4]

    const int nCh = K >> 5;
    // fill thread mapping: row = tid>>1, logical chunks {2*(tid&1), +1}
    int frow = tid >> 1;
    int fc0 = (tid & 1) << 1;
    uint32_t fsw = (uint32_t)((frow >> 1) & 3);

    auto loadStage = [&](int stg, int c) {
        if (c < nCh) {
            uint32_t st = sb + stg * STG3;
            int k0 = c << 5;
            size_t abase = (size_t)(row0 + frow) * K + k0;
            size_t bbase = (size_t)(col0 + frow) * K + k0;
#pragma unroll
            for (int cc = 0; cc < 2; cc++) {
                int cl = fc0 + cc;
                uint32_t doff = (uint32_t)(frow << 6) + ((cl ^ fsw) << 4);
                cpasync16(st + doff,         Ahi + abase + (cl << 3));
                cpasync16(st + 8192 + doff,  Alo + abase + (cl << 3));
                cpasync16(st + 16384 + doff, Bhi + bbase + (cl << 3));
                cpasync16(st + 24576 + doff, Blo + bbase + (cl << 3));
            }
        }
        asm volatile("cp.async.commit_group;" ::: "memory");
    };

    // per-lane ldsm row indices (fixed across chunks)
    int arow[4], brow[2];
    uint32_t asw[4], bsw[2];
#pragma unroll
    for (int mf = 0; mf < 4; mf++) {
        arow[mf] = (wm << 6) + (mf << 4) + (lane & 15);
        asw[mf] = (uint32_t)((arow[mf] >> 1) & 3);
    }
#pragma unroll
    for (int g = 0; g < 2; g++) {
        brow[g] = (wn << 5) + (g << 4) + (lane & 7) + (((lane >> 3) & 1) << 3);
        bsw[g] = (uint32_t)((brow[g] >> 1) & 3);
    }
    int kc = lane >> 4;   // 0/1: which k8 chunk within ks

    loadStage(0, 0);
    loadStage(1, 1);

    int stg = 0;
    for (int c = 0; c < nCh; ++c) {
        asm volatile("cp.async.wait_group 1;" ::: "memory");
        __syncthreads();
        uint32_t st = sb + stg * STG3;
#pragma unroll
        for (int ks = 0; ks < 2; ks++) {
            int cl = (ks << 1) + kc;
            uint32_t ah[4][4], al[4][4];
#pragma unroll
            for (int mf = 0; mf < 4; mf++) {
                uint32_t ad = st + (uint32_t)(arow[mf] << 6) + (((uint32_t)cl ^ asw[mf]) << 4);
                ldsm4(ah[mf], ad);
                ldsm4(al[mf], ad + 8192);
            }
            uint32_t bh[2][4], bl[2][4];
#pragma unroll
            for (int g = 0; g < 2; g++) {
                uint32_t bd = st + 16384 + (uint32_t)(brow[g] << 6) + (((uint32_t)cl ^ bsw[g]) << 4);
                ldsm4(bh[g], bd);
                ldsm4(bl[g], bd + 8192);
            }
            // term-outer ordering: no back-to-back same-acc MMAs
#pragma unroll
            for (int mf = 0; mf < 4; mf++)
#pragma unroll
                for (int nf = 0; nf < 4; nf++)
                    mma16816(accv[mf][nf], ah[mf], bh[nf >> 1][nf & 1], bh[nf >> 1][(nf & 1) + 2]);
#pragma unroll
            for (int mf = 0; mf < 4; mf++)
#pragma unroll
                for (int nf = 0; nf < 4; nf++)
                    mma16816(accv[mf][nf], ah[mf], bl[nf >> 1][nf & 1], bl[nf >> 1][(nf & 1) + 2]);
#pragma unroll
            for (int mf = 0; mf < 4; mf++)
#pragma unroll
                for (int nf = 0; nf < 4; nf++)
                    mma16816(accv[mf][nf], al[mf], bh[nf >> 1][nf & 1], bh[nf >> 1][(nf & 1) + 2]);
        }
        loadStage(stg == 0 ? 2 : stg - 1, c + 2);
        stg = (stg == 2) ? 0 : stg + 1;
    }

    // ---- epilogue ----
#pragma unroll
    for (int mf = 0; mf < 4; mf++) {
        int rbase = row0 + (wm << 6) + (mf << 4) + (lane >> 2);
#pragma unroll
        for (int nf = 0; nf < 4; nf++) {
            int cb = col0 + (wn << 5) + (nf << 3) + ((lane & 3) << 1);
            float b0 = bias ? bias[cb] : 0.f;
            float b1 = bias ? bias[cb + 1] : 0.f;
#pragma unroll
            for (int half = 0; half < 2; half++) {
                int r = rbase + (half << 3);
                float v0 = accv[mf][nf][half * 2 + 0] + b0;
                float v1 = accv[mf][nf][half * 2 + 1] + b1;
                size_t gi = (size_t)r * N + cb;
                if (relu) { v0 = fmaxf(v0, 0.f); v1 = fmaxf(v1, 0.f); }
                if (Chi) {
                    __nv_bfloat162 h = __floats2bfloat162_rn(v0, v1);
                    float2 hf = __bfloat1622float2(h);
                    __nv_bfloat162 l = __floats2bfloat162_rn(v0 - hf.x, v1 - hf.y);
                    *(__nv_bfloat162*)(Chi + gi) = h;
                    *(__nv_bfloat162*)(Clo + gi) = l;
                } else {
                    if (resid) { v0 += resid[gi]; v1 += resid[gi + 1]; }
                    *(float2*)(C + gi) = make_float2(v0, v1);
                }
            }
        }
    }
}

// ---------------- flash-style causal attention (fp32 -> bf16 hi/lo out) ------
__global__ __launch_bounds__(256) void attn_kernel(const float* __restrict__ qkv,
                                                   __nv_bfloat16* __restrict__ ohi,
                                                   __nv_bfloat16* __restrict__ olo) {
    __shared__ float sQP[64][64];
    __shared__ float sK[64][64];
    __shared__ float sVt[64][64];
    int tid = threadIdx.x;
    int qt = blockIdx.x;
    int bh = blockIdx.y;
    int bb = bh / H_, hh = bh % H_;
    int r = tid >> 2, quarter = tid & 3;
    int cbase = quarter << 4;
    size_t rowbase = (size_t)(bb * T_ + (qt << 6));
    const float* q = qkv + hh * 64;
    const float* k = qkv + E_ + hh * 64;
    const float* v = qkv + 2 * E_ + hh * 64;

    for (int i = tid; i < 4096; i += 256) {
        int rr = i >> 6, cc = i & 63;
        sQP[rr][cc] = q[(rowbase + rr) * (size_t)NQKV + cc];
    }
    __syncthreads();
    float qreg[64];
#pragma unroll
    for (int i = 0; i < 16; i++) {
        float4 t4 = *(const float4*)&sQP[r][i << 2];
        qreg[i * 4 + 0] = t4.x * 0.125f; qreg[i * 4 + 1] = t4.y * 0.125f;
        qreg[i * 4 + 2] = t4.z * 0.125f; qreg[i * 4 + 3] = t4.w * 0.125f;
    }
    float m = -INFINITY, lsum = 0.f;
    float oacc[16];
#pragma unroll
    for (int j = 0; j < 16; j++) oacc[j] = 0.f;
    int qi = (qt << 6) + r;

    for (int kt = 0; kt <= qt; kt++) {
        __syncthreads();
        size_t kbase = (size_t)(bb * T_ + (kt << 6));
        for (int i = tid; i < 4096; i += 256) {
            int rr = i >> 6, cc = i & 63;
            sK[rr][cc]  = k[(kbase + rr) * (size_t)NQKV + cc];
            sVt[cc][rr] = v[(kbase + rr) * (size_t)NQKV + cc];
        }
        __syncthreads();

        float s[16];
#pragma unroll
        for (int j = 0; j < 16; j++) s[j] = 0.f;
#pragma unroll
        for (int kk = 0; kk < 64; kk += 4) {
#pragma unroll
            for (int j = 0; j < 16; j++) {
                float4 k4 = *(const float4*)&sK[cbase + j][kk];
                s[j] += qreg[kk] * k4.x + qreg[kk + 1] * k4.y +
                        qreg[kk + 2] * k4.z + qreg[kk + 3] * k4.w;
            }
        }
        if (kt == qt) {
#pragma unroll
            for (int j = 0; j < 16; j++)
                if ((kt << 6) + cbase + j > qi) s[j] = -INFINITY;
        }
        float mt = s[0];
#pragma unroll
        for (int j = 1; j < 16; j++) mt = fmaxf(mt, s[j]);
        mt = fmaxf(mt, __shfl_xor_sync(0xffffffffu, mt, 1));
        mt = fmaxf(mt, __shfl_xor_sync(0xffffffffu, mt, 2));
        float mnew = fmaxf(m, mt);
        float alpha = __expf(m - mnew);
        float psum = 0.f;
        float p[16];
#pragma unroll
        for (int j = 0; j < 16; j++) { p[j] = __expf(s[j] - mnew); psum += p[j]; }
        psum += __shfl_xor_sync(0xffffffffu, psum, 1);
        psum += __shfl_xor_sync(0xffffffffu, psum, 2);
        lsum = lsum * alpha + psum;
        m = mnew;
#pragma unroll
        for (int j = 0; j < 16; j++) oacc[j] *= alpha;
#pragma unroll
        for (int j = 0; j < 16; j++) sQP[r][cbase + j] = p[j];
        __syncthreads();
#pragma unroll
        for (int c0 = 0; c0 < 64; c0 += 16) {
            float pc[16];
#pragma unroll
            for (int ii = 0; ii < 4; ii++) {
                float4 p4 = *(const float4*)&sQP[r][c0 + (ii << 2)];
                pc[ii * 4 + 0] = p4.x; pc[ii * 4 + 1] = p4.y;
                pc[ii * 4 + 2] = p4.z; pc[ii * 4 + 3] = p4.w;
            }
#pragma unroll
            for (int j = 0; j < 16; j++) {
                int d = cbase + j;
#pragma unroll
                for (int cc = 0; cc < 16; cc += 4) {
                    float4 v4 = *(const float4*)&sVt[d][c0 + cc];
                    oacc[j] += pc[cc] * v4.x + pc[cc + 1] * v4.y +
                               pc[cc + 2] * v4.z + pc[cc + 3] * v4.w;
                }
            }
        }
    }
    float linv = 1.f / lsum;
    size_t obase = (rowbase + r) * (size_t)E_ + hh * 64 + cbase;
#pragma unroll
    for (int j = 0; j < 16; j += 2) {
        float v0 = oacc[j] * linv, v1 = oacc[j + 1] * linv;
        __nv_bfloat162 h = __floats2bfloat162_rn(v0, v1);
        float2 hf = __bfloat1622float2(h);
        __nv_bfloat162 l = __floats2bfloat162_rn(v0 - hf.x, v1 - hf.y);
        *(__nv_bfloat162*)(ohi + obase + j) = h;
        *(__nv_bfloat162*)(olo + obase + j) = l;
    }
}

// ---------------- loss ------------------------------------------------------
__global__ __launch_bounds__(256) void row_lse_kernel(const float* __restrict__ logits,
                                                      const int* __restrict__ targets,
                                                      float* __restrict__ rowloss) {
    int row = blockIdx.x, tid = threadIdx.x;
    const float* lr = logits + (size_t)row * V_;
    float mx = -INFINITY;
    for (int i = tid; i < V_; i += 256) mx = fmaxf(mx, lr[i]);
#pragma unroll
    for (int o = 16; o > 0; o >>= 1) mx = fmaxf(mx, __shfl_xor_sync(0xffffffffu, mx, o));
    __shared__ float sm[8];
    if ((tid & 31) == 0) sm[tid >> 5] = mx;
    __syncthreads();
    float m2 = -INFINITY;
#pragma unroll
    for (int i = 0; i < 8; i++) m2 = fmaxf(m2, sm[i]);
    float se = 0.f;
    for (int i = tid; i < V_; i += 256) se += __expf(lr[i] - m2);
#pragma unroll
    for (int o = 16; o > 0; o >>= 1) se += __shfl_xor_sync(0xffffffffu, se, o);
    __shared__ float ssum[8];
    if ((tid & 31) == 0) ssum[tid >> 5] = se;
    __syncthreads();
    if (tid == 0) {
        float tot = 0.f;
#pragma unroll
        for (int i = 0; i < 8; i++) tot += ssum[i];
        rowloss[row] = (logf(tot) + m2) - lr[targets[row]];
    }
}

__global__ __launch_bounds__(256) void loss_reduce_kernel(const float* __restrict__ rowloss,
                                                          float* __restrict__ out) {
    int tid = threadIdx.x;
    float s = 0.f;
    for (int i = tid; i < BT; i += 256) s += rowloss[i];
#pragma unroll
    for (int o = 16; o > 0; o >>= 1) s += __shfl_xor_sync(0xffffffffu, s, o);
    __shared__ float sm[8];
    if ((tid & 31) == 0) sm[tid >> 5] = s;
    __syncthreads();
    if (tid == 0) {
        float t = 0.f;
#pragma unroll
        for (int i = 0; i < 8; i++) t += sm[i];
        out[0] = t * (1.f / BT);
    }
}

// ---------------- launch ----------------------------------------------------
extern "C" void kernel_launch(void* const* d_in, const int* in_sizes, int n_in,
                              void* d_out, int out_size) {
    const int*   idx     = (const int*)d_in[0];
    const int*   targets = (const int*)d_in[1];
    const float* tok_emb = (const float*)d_in[2];
    const float* pos_emb = (const float*)d_in[3];
    const float* Wq  = (const float*)d_in[4];
    const float* bq  = (const float*)d_in[5];
    const float* Wk  = (const float*)d_in[6];
    const float* bk  = (const float*)d_in[7];
    const float* Wv  = (const float*)d_in[8];
    const float* bv  = (const float*)d_in[9];
    const float* Wo  = (const float*)d_in[10];
    const float* bo  = (const float*)d_in[11];
    const float* ln1g = (const float*)d_in[12];
    const float* ln1b = (const float*)d_in[13];
    const float* W1  = (const float*)d_in[14];
    const float* b1  = (const float*)d_in[15];
    const float* W2  = (const float*)d_in[16];
    const float* b2  = (const float*)d_in[17];
    const float* ln2g = (const float*)d_in[18];
    const float* ln2b = (const float*)d_in[19];
    const float* lnfg = (const float*)d_in[20];
    const float* lnfb = (const float*)d_in[21];
    const float* Wlm = (const float*)d_in[22];
    const float* blm = (const float*)d_in[23];
    float* out = (float*)d_out;

    float *px, *pqkv, *pwq, *pwk, *pwv, *pbqkv, *prl, *plg;
    __nv_bfloat16 *phhi, *phlo, *pohi, *polo, *pffhi, *pfflo, *pwthi, *pwtlo;
    cudaGetSymbolAddress((void**)&px,    g_x);
    cudaGetSymbolAddress((void**)&pqkv,  g_qkv);
    cudaGetSymbolAddress((void**)&phhi,  g_hhi);
    cudaGetSymbolAddress((void**)&phlo,  g_hlo);
    cudaGetSymbolAddress((void**)&pohi,  g_ohi);
    cudaGetSymbolAddress((void**)&polo,  g_olo);
    cudaGetSymbolAddress((void**)&pffhi, g_ffhi);
    cudaGetSymbolAddress((void**)&pfflo, g_fflo);
    cudaGetSymbolAddress((void**)&pwq,   g_wq);
    cudaGetSymbolAddress((void**)&pwk,   g_wk);
    cudaGetSymbolAddress((void**)&pwv,   g_wv);
    cudaGetSymbolAddress((void**)&pbqkv, g_bqkv);
    cudaGetSymbolAddress((void**)&pwthi, g_wthi);
    cudaGetSymbolAddress((void**)&pwtlo, g_wtlo);
    cudaGetSymbolAddress((void**)&prl,   g_rowloss);
    cudaGetSymbolAddress((void**)&plg,   g_logits_scratch);

    cudaFuncSetAttribute(gemm_tc_kernel, cudaFuncAttributeMaxDynamicSharedMemorySize, GEMM_SMEM);

    const long long NLOG = (long long)BT * V_;
    float* logits = (out_size >= NLOG) ? out : plg;

    // --- weight prep (every call; part of the graph) ---
    int nrep = L_ * H_ * E_ * HS_;
    int grep = (nrep + 255) / 256;
    repack_qkv_kernel<<<grep, 256>>>(Wq, pwq);
    repack_qkv_kernel<<<grep, 256>>>(Wk, pwk);
    repack_qkv_kernel<<<grep, 256>>>(Wv, pwv);
    biascat_kernel<<<(L_ * NQKV + 255) / 256, 256>>>(bq, bk, bv, pbqkv);

    dim3 cb(32, 8);
    for (int l = 0; l < L_; l++) {
        size_t wel = (size_t)l * E_ * E_;
        wconvt_kernel<<<dim3(E_ / 32, E_ / 32), cb>>>(pwq + wel, pwthi + OFF_QKV(l),           pwtlo + OFF_QKV(l),           E_, E_);
        wconvt_kernel<<<dim3(E_ / 32, E_ / 32), cb>>>(pwk + wel, pwthi + OFF_QKV(l) + 589824,  pwtlo + OFF_QKV(l) + 589824,  E_, E_);
        wconvt_kernel<<<dim3(E_ / 32, E_ / 32), cb>>>(pwv + wel, pwthi + OFF_QKV(l) + 1179648, pwtlo + OFF_QKV(l) + 1179648, E_, E_);
        wconvt_kernel<<<dim3(E_ / 32, E_ / 32), cb>>>(Wo + wel,  pwthi + OFF_O(l),             pwtlo + OFF_O(l),             E_, E_);
        wconvt_kernel<<<dim3(FF / 32, E_ / 32), cb>>>(W1 + (size_t)l * E_ * FF, pwthi + OFF_W1(l), pwtlo + OFF_W1(l), E_, FF);
        wconvt_kernel<<<dim3(E_ / 32, FF / 32), cb>>>(W2 + (size_t)l * FF * E_, pwthi + OFF_W2(l), pwtlo + OFF_W2(l), FF, E_);
    }
    wconvt_kernel<<<dim3(V_ / 32, E_ / 32), cb>>>(Wlm, pwthi + OFF_LM, pwtlo + OFF_LM, E_, V_);

    // --- forward ---
    embed_kernel<<<(BT * E_) / 256, 256>>>(idx, tok_emb, pos_emb, px);

    dim3 gQKV(NQKV / 128, BT / 128);
    dim3 gE(E_ / 128, BT / 128);
    dim3 gF(FF / 128, BT / 128);
    dim3 gV(V_ / 128, BT / 128);
    for (int l = 0; l < L_; l++) {
        ln_kernel<<<BT, 256>>>(px, ln1g + l * E_, ln1b + l * E_, phhi, phlo);
        gemm_tc_kernel<<<gQKV, 256, GEMM_SMEM>>>(phhi, phlo,
            pwthi + OFF_QKV(l), pwtlo + OFF_QKV(l), pbqkv + l * NQKV, nullptr,
            pqkv, nullptr, nullptr, NQKV, E_, 0);
        attn_kernel<<<dim3(T_ / 64, B_ * H_), 256>>>(pqkv, pohi, polo);
        gemm_tc_kernel<<<gE, 256, GEMM_SMEM>>>(pohi, polo,
            pwthi + OFF_O(l), pwtlo + OFF_O(l), bo + l * E_, px,
            px, nullptr, nullptr, E_, E_, 0);
        ln_kernel<<<BT, 256>>>(px, ln2g + l * E_, ln2b + l * E_, phhi, phlo);
        gemm_tc_kernel<<<gF, 256, GEMM_SMEM>>>(phhi, phlo,
            pwthi + OFF_W1(l), pwtlo + OFF_W1(l), b1 + l * FF, nullptr,
            nullptr, pffhi, pfflo, FF, E_, 1);
        gemm_tc_kernel<<<gE, 256, GEMM_SMEM>>>(pffhi, pfflo,
            pwthi + OFF_W2(l), pwtlo + OFF_W2(l), b2 + l * E_, px,
            px, nullptr, nullptr, E_, FF, 0);
    }
    ln_kernel<<<BT, 256>>>(px, lnfg, lnfb, phhi, phlo);
    gemm_tc_kernel<<<gV, 256, GEMM_SMEM>>>(phhi, phlo,
        pwthi + OFF_LM, pwtlo + OFF_LM, blm, nullptr,
        logits, nullptr, nullptr, V_, E_, 0);

    // --- loss ---
    float* loss_dst = nullptr;
    if (out_size == 1)        loss_dst = out;
    else if (out_size > NLOG) loss_dst = out + NLOG;
    if (loss_dst) {
        row_lse_kernel<<<BT, 256>>>(logits, targets, prl);
        loss_reduce_kernel<<<1, 256>>>(prl, loss_dst);
    }
}